// round 7
// baseline (speedup 1.0000x reference)
#include <cuda_runtime.h>

#define NSD 16
#define NVD 8
#define HED 32
#define DD  40
#define WND 640
#define MAXN 10000
#define MAXE 160000
#define EPSV 1e-5f
#define TPB2 512
#define ROWS 512
#define SM_W2 20480
#define SM_W1 1024
#define SM_FLOATS (SM_W2 + SM_W1 + 32 + WND + ROWS * 41)

typedef unsigned long long u64t;

__device__ __constant__ float kC110 = 0.57735026918962576f;
__device__ __constant__ float kC111 = 0.70710678118654752f;

__device__ float    d_qnode[MAXN * DD];
__device__ float    d_attn [MAXE];
__device__ float    d_vedge[MAXE * DD];
__device__ unsigned d_nmax [MAXN];
__device__ float    d_denom[MAXN];
__device__ float    d_upd  [MAXN * DD];
__device__ float    d_ybuf [MAXN * DD];
__device__ float    d_gstats[48];
__device__ float    d_bnp  [48];

__device__ __forceinline__ unsigned encf(float f) {
    unsigned u = __float_as_uint(f);
    return (u & 0x80000000u) ? ~u : (u | 0x80000000u);
}
__device__ __forceinline__ float decf(unsigned u) {
    return (u & 0x80000000u) ? __uint_as_float(u ^ 0x80000000u) : __uint_as_float(~u);
}
__device__ __forceinline__ u64t pk(float lo, float hi) {
    u64t r;
    asm("mov.b64 %0, {%1, %2};" : "=l"(r) : "f"(lo), "f"(hi));
    return r;
}
__device__ __forceinline__ void upk(u64t v, float& lo, float& hi) {
    asm("mov.b64 {%0, %1}, %2;" : "=f"(lo), "=f"(hi) : "l"(v));
}
__device__ __forceinline__ u64t ffma2(u64t a, u64t b, u64t c) {
    u64t d;
    asm("fma.rn.f32x2 %0, %1, %2, %3;" : "=l"(d) : "l"(a), "l"(b), "l"(c));
    return d;
}

__global__ void k_init(int n_nodes) {
    int i = blockIdx.x * blockDim.x + threadIdx.x;
    if (i < n_nodes * DD) d_upd[i] = 0.f;
    if (i < n_nodes) { d_denom[i] = 0.f; d_nmax[i] = 0u; }
    if (i < 48) d_gstats[i] = 0.f;
}

__global__ void k_qnode(const float* __restrict__ atom, const float* __restrict__ Wqs,
                        const float* __restrict__ Wqv, int n_nodes) {
    int n = blockIdx.x * blockDim.x + threadIdx.x;
    if (n >= n_nodes) return;
    const float* a = atom + n * DD;
    float qs[16], qv[24];
#pragma unroll
    for (int o = 0; o < 16; o++) qs[o] = 0.f;
#pragma unroll
    for (int c = 0; c < 24; c++) qv[c] = 0.f;
    for (int i = 0; i < 16; i++) {
        float x = __ldg(a + i);
#pragma unroll
        for (int o = 0; o < 16; o++) qs[o] = fmaf(x, __ldg(Wqs + i * 16 + o), qs[o]);
    }
    for (int i = 0; i < 8; i++) {
        float x0 = __ldg(a + 16 + 3 * i), x1 = __ldg(a + 17 + 3 * i), x2 = __ldg(a + 18 + 3 * i);
#pragma unroll
        for (int o = 0; o < 8; o++) {
            float w = __ldg(Wqv + i * 8 + o);
            qv[3 * o + 0] = fmaf(w, x0, qv[3 * o + 0]);
            qv[3 * o + 1] = fmaf(w, x1, qv[3 * o + 1]);
            qv[3 * o + 2] = fmaf(w, x2, qv[3 * o + 2]);
        }
    }
    float* q = d_qnode + n * DD;
#pragma unroll
    for (int o = 0; o < 16; o++) q[o] = qs[o];
#pragma unroll
    for (int c = 0; c < 24; c++) q[16 + c] = qv[c];
}

// packed GEMV, one edge: per j = 1 LDS.128 + 1 MOV64 + 2 FFMA2 (4 MACs)
__device__ __forceinline__ void gemv4_1p(const float* __restrict__ sW2,
                                         const float* __restrict__ sB2,
                                         const float* h, int n,
                                         u64t& a01, u64t& a23) {
    ulonglong2 bb = *reinterpret_cast<const ulonglong2*>(sB2 + n);
    a01 = bb.x; a23 = bb.y;
#pragma unroll
    for (int j = 0; j < HED; j++) {
        ulonglong2 r = *reinterpret_cast<const ulonglong2*>(sW2 + j * WND + n);
        u64t hj = pk(h[j], h[j]);
        a01 = ffma2(r.x, hj, a01);
        a23 = ffma2(r.y, hj, a23);
    }
}

template <bool IS_K>
__global__ void __launch_bounds__(TPB2, 1) k_edge(
    const float* __restrict__ atom, const float* __restrict__ ef,
    const float* __restrict__ sh, const int* __restrict__ ei,
    const float* __restrict__ W1, const float* __restrict__ B1,
    const float* __restrict__ W2, const float* __restrict__ B2,
    int n_edges)
{
    extern __shared__ float sm[];
    float* sW2 = sm;
    float* sW1 = sm + SM_W2;
    float* sB1 = sW1 + SM_W1;
    float* sB2 = sB1 + 32;
    float* stage = sB2 + WND;
    const int t = threadIdx.x;

    for (int i = t; i < SM_W2 / 4; i += TPB2)
        reinterpret_cast<float4*>(sW2)[i] = __ldg(reinterpret_cast<const float4*>(W2) + i);
    for (int i = t; i < SM_W1 / 4; i += TPB2)
        reinterpret_cast<float4*>(sW1)[i] = __ldg(reinterpret_cast<const float4*>(W1) + i);
    if (t < 32) sB1[t] = __ldg(B1 + t);
    for (int i = t; i < WND; i += TPB2) sB2[i] = __ldg(B2 + i);

    const int e0 = blockIdx.x * ROWS;
    {
        const int lim = n_edges * HED;
        for (int l = t; l < ROWS * HED; l += TPB2) {
            int g = e0 * HED + l;
            stage[(l >> 5) * 41 + (l & 31)] = (g < lim) ? __ldg(ef + g) : 0.f;
        }
    }
    __syncthreads();

    float h[32];
    {
        const float* myef = stage + t * 41;
#pragma unroll
        for (int j = 0; j < 32; j++) h[j] = sB1[j];
#pragma unroll 4
        for (int i = 0; i < 32; i++) {
            float x = myef[i];
#pragma unroll
            for (int j4 = 0; j4 < 8; j4++) {
                float4 r = *reinterpret_cast<const float4*>(sW1 + i * 32 + 4 * j4);
                h[4 * j4 + 0] = fmaf(x, r.x, h[4 * j4 + 0]);
                h[4 * j4 + 1] = fmaf(x, r.y, h[4 * j4 + 1]);
                h[4 * j4 + 2] = fmaf(x, r.z, h[4 * j4 + 2]);
                h[4 * j4 + 3] = fmaf(x, r.w, h[4 * j4 + 3]);
            }
        }
#pragma unroll
        for (int j = 0; j < 32; j++) h[j] = fmaxf(h[j], 0.f);
    }
    __syncthreads();

    const int e = e0 + t;
    const bool valid = e < n_edges;
    int src = 0;
    float shs = 0.f, s0 = 0.f, s1 = 0.f, s2 = 0.f;
    if (valid) {
        int dst = __ldg(ei + e);
        src = __ldg(ei + n_edges + e);
        float4 s4 = __ldg(reinterpret_cast<const float4*>(sh) + e);
        shs = s4.x; s0 = s4.y; s1 = s4.z; s2 = s4.w;
        const float4* ar = reinterpret_cast<const float4*>(atom + dst * DD);
        float* stw = stage + t * 41;
#pragma unroll
        for (int i = 0; i < 10; i++) {
            float4 v = __ldg(ar + i);
            stw[4 * i] = v.x; stw[4 * i + 1] = v.y; stw[4 * i + 2] = v.z; stw[4 * i + 3] = v.w;
        }
    }
    __syncthreads();

    const float* st = stage + t * 41;
    // packed accumulators: osp[2*o4+hh] = scalar outs (4o4+2hh, +1)
    // ovp[o4*6+hh*3+d] = vector outs o=(4o4+2hh, +1), dim d
    u64t osp[8], ovp[12];
#pragma unroll
    for (int i = 0; i < 8; i++) osp[i] = 0ull;
#pragma unroll
    for (int i = 0; i < 12; i++) ovp[i] = 0ull;

#pragma unroll 1
    for (int i2 = 0; i2 < 24; i2++) {
        float a;
        if (i2 < 16) {
            a = st[i2] * shs;
        } else {
            const float* xv = st + 16 + 3 * (i2 - 16);
            a = kC110 * (xv[0] * s0 + xv[1] * s1 + xv[2] * s2);
        }
        u64t a2 = pk(a, a);
        const int nb = i2 * 16;
#pragma unroll
        for (int o4 = 0; o4 < 4; o4++) {
            u64t w01, w23;
            gemv4_1p(sW2, sB2, h, nb + 4 * o4, w01, w23);
            osp[2 * o4 + 0] = ffma2(w01, a2, osp[2 * o4 + 0]);
            osp[2 * o4 + 1] = ffma2(w23, a2, osp[2 * o4 + 1]);
        }
    }
#pragma unroll 1
    for (int i3 = 0; i3 < 32; i3++) {
        float m0, m1, m2;
        if (i3 < 16) {
            float x = st[i3];
            m0 = x * s0; m1 = x * s1; m2 = x * s2;
        } else if (i3 < 24) {
            const float* xv = st + 16 + 3 * (i3 - 16);
            m0 = xv[0] * shs; m1 = xv[1] * shs; m2 = xv[2] * shs;
        } else {
            const float* xv = st + 16 + 3 * (i3 - 24);
            m0 = kC111 * (xv[1] * s2 - xv[2] * s1);
            m1 = kC111 * (xv[2] * s0 - xv[0] * s2);
            m2 = kC111 * (xv[0] * s1 - xv[1] * s0);
        }
        u64t m0d = pk(m0, m0), m1d = pk(m1, m1), m2d = pk(m2, m2);
        const int nb = 384 + i3 * 8;
#pragma unroll
        for (int o4 = 0; o4 < 2; o4++) {
            u64t w01, w23;
            gemv4_1p(sW2, sB2, h, nb + 4 * o4, w01, w23);
            const int base = o4 * 6;
            ovp[base + 0] = ffma2(w01, m0d, ovp[base + 0]);
            ovp[base + 1] = ffma2(w01, m1d, ovp[base + 1]);
            ovp[base + 2] = ffma2(w01, m2d, ovp[base + 2]);
            ovp[base + 3] = ffma2(w23, m0d, ovp[base + 3]);
            ovp[base + 4] = ffma2(w23, m1d, ovp[base + 4]);
            ovp[base + 5] = ffma2(w23, m2d, ovp[base + 5]);
        }
    }

    if (!valid) return;

    if (IS_K) {
        const float* q = d_qnode + src * DD;
        float attn = 0.f;
#pragma unroll
        for (int o4 = 0; o4 < 4; o4++)
#pragma unroll
            for (int hh = 0; hh < 2; hh++) {
                float lo, hi; upk(osp[2 * o4 + hh], lo, hi);
                int o = 4 * o4 + 2 * hh;
                attn = fmaf(lo, __ldg(q + o), attn);
                attn = fmaf(hi, __ldg(q + o + 1), attn);
            }
#pragma unroll
        for (int o4 = 0; o4 < 2; o4++)
#pragma unroll
            for (int hh = 0; hh < 2; hh++)
#pragma unroll
                for (int d = 0; d < 3; d++) {
                    float lo, hi; upk(ovp[o4 * 6 + hh * 3 + d], lo, hi);
                    int o = 4 * o4 + 2 * hh;
                    attn = fmaf(lo, __ldg(q + 16 + 3 * o + d), attn);
                    attn = fmaf(hi, __ldg(q + 16 + 3 * (o + 1) + d), attn);
                }
        d_attn[e] = attn;
        atomicMax(&d_nmax[src], encf(attn));
    } else {
#pragma unroll
        for (int o4 = 0; o4 < 4; o4++)
#pragma unroll
            for (int hh = 0; hh < 2; hh++) {
                float lo, hi; upk(osp[2 * o4 + hh], lo, hi);
                int o = 4 * o4 + 2 * hh;
                d_vedge[o * n_edges + e] = lo;
                d_vedge[(o + 1) * n_edges + e] = hi;
            }
#pragma unroll
        for (int o4 = 0; o4 < 2; o4++)
#pragma unroll
            for (int hh = 0; hh < 2; hh++)
#pragma unroll
                for (int d = 0; d < 3; d++) {
                    float lo, hi; upk(ovp[o4 * 6 + hh * 3 + d], lo, hi);
                    int o = 4 * o4 + 2 * hh;
                    d_vedge[(16 + 3 * o + d) * n_edges + e] = lo;
                    d_vedge[(16 + 3 * (o + 1) + d) * n_edges + e] = hi;
                }
    }
}

__global__ void k_soft(const int* __restrict__ ei, int n_edges) {
    int e = blockIdx.x * blockDim.x + threadIdx.x;
    if (e >= n_edges) return;
    int src = __ldg(ei + n_edges + e);
    float m = decf(d_nmax[src]);
    float a = expf(d_attn[e] - m);
    atomicAdd(&d_denom[src], a);
    float* u = d_upd + src * DD;
#pragma unroll
    for (int c = 0; c < DD; c++)
        atomicAdd(u + c, a * d_vedge[c * n_edges + e]);
}

__global__ void k_stats(const float* __restrict__ atom, int n_nodes) {
    __shared__ float red[40];
    int t = threadIdx.x;
    if (t < 40) red[t] = 0.f;
    __syncthreads();
    int n = blockIdx.x * blockDim.x + t;
    float y[40];
    if (n < n_nodes) {
        float den = d_denom[n];
        float inv = den > 0.f ? 1.f / den : 0.f;
#pragma unroll
        for (int c = 0; c < 40; c++) {
            y[c] = atom[n * DD + c] + d_upd[n * DD + c] * inv;
            d_ybuf[n * DD + c] = y[c];
        }
    } else {
#pragma unroll
        for (int c = 0; c < 40; c++) y[c] = 0.f;
    }
    const unsigned full = 0xffffffffu;
#pragma unroll
    for (int c = 0; c < 16; c++) {
        float v = y[c], v2 = v * v;
#pragma unroll
        for (int o = 16; o > 0; o >>= 1) {
            v  += __shfl_down_sync(full, v, o);
            v2 += __shfl_down_sync(full, v2, o);
        }
        if ((t & 31) == 0) { atomicAdd(&red[c], v); atomicAdd(&red[16 + c], v2); }
    }
#pragma unroll
    for (int i = 0; i < 8; i++) {
        float v = y[16 + 3 * i] * y[16 + 3 * i] + y[17 + 3 * i] * y[17 + 3 * i]
                + y[18 + 3 * i] * y[18 + 3 * i];
#pragma unroll
        for (int o = 16; o > 0; o >>= 1) v += __shfl_down_sync(full, v, o);
        if ((t & 31) == 0) atomicAdd(&red[32 + i], v);
    }
    __syncthreads();
    if (t < 40) atomicAdd(&d_gstats[t], red[t]);
}

__global__ void k_bn(const float* __restrict__ ws, const float* __restrict__ bs,
                     const float* __restrict__ wv, int n_nodes) {
    int t = threadIdx.x;
    float N = (float)n_nodes;
    if (t < 16) {
        float mu  = d_gstats[t] / N;
        float var = d_gstats[16 + t] / N - mu * mu;
        float A = __ldg(ws + t) / sqrtf(var + EPSV);
        d_bnp[t] = A;
        d_bnp[16 + t] = __ldg(bs + t) - mu * A;
    } else if (t < 24) {
        int i = t - 16;
        float norm = d_gstats[32 + i] / (3.f * N);
        d_bnp[32 + i] = __ldg(wv + i) / sqrtf(norm + EPSV);
    }
}

__global__ void k_out(float* __restrict__ out, int n_nodes) {
    int idx = blockIdx.x * blockDim.x + threadIdx.x;
    if (idx >= n_nodes * DD) return;
    int c = idx % DD;
    float y = d_ybuf[idx];
    out[idx] = (c < 16) ? (y * d_bnp[c] + d_bnp[16 + c])
                        : (y * d_bnp[32 + (c - 16) / 3]);
}

__global__ void k_copy(const float* __restrict__ src, float* __restrict__ dst, int n4) {
    int i = blockIdx.x * blockDim.x + threadIdx.x;
    if (i < n4)
        reinterpret_cast<float4*>(dst)[i] = __ldg(reinterpret_cast<const float4*>(src) + i);
}

extern "C" void kernel_launch(void* const* d_in, const int* in_sizes, int n_in,
                              void* d_out, int out_size) {
    const float* atom = (const float*)d_in[0];
    const float* ef   = (const float*)d_in[1];
    const float* sh   = (const float*)d_in[2];
    const float* Wqs  = (const float*)d_in[3];
    const float* Wqv  = (const float*)d_in[4];
    const float* kw1  = (const float*)d_in[5];
    const float* kb1  = (const float*)d_in[6];
    const float* kw2  = (const float*)d_in[7];
    const float* kb2  = (const float*)d_in[8];
    const float* vw1  = (const float*)d_in[9];
    const float* vb1  = (const float*)d_in[10];
    const float* vw2  = (const float*)d_in[11];
    const float* vb2  = (const float*)d_in[12];
    const float* bnws = (const float*)d_in[13];
    const float* bnbs = (const float*)d_in[14];
    const float* bnwv = (const float*)d_in[15];
    const int*   ei   = (const int*)d_in[16];

    int n_nodes = in_sizes[0] / DD;
    int n_edges = in_sizes[1] / HED;
    float* out = (float*)d_out;

    size_t smem = SM_FLOATS * sizeof(float);
    cudaFuncSetAttribute(k_edge<true>,  cudaFuncAttributeMaxDynamicSharedMemorySize, (int)smem);
    cudaFuncSetAttribute(k_edge<false>, cudaFuncAttributeMaxDynamicSharedMemorySize, (int)smem);

    k_init<<<(n_nodes * DD + 255) / 256, 256>>>(n_nodes);
    k_qnode<<<(n_nodes + 255) / 256, 256>>>(atom, Wqs, Wqv, n_nodes);

    int eb = (n_edges + ROWS - 1) / ROWS;
    k_edge<true><<<eb, TPB2, smem>>>(atom, ef, sh, ei, kw1, kb1, kw2, kb2, n_edges);
    k_edge<false><<<eb, TPB2, smem>>>(atom, ef, sh, ei, vw1, vb1, vw2, vb2, n_edges);

    k_soft<<<(n_edges + 255) / 256, 256>>>(ei, n_edges);
    k_stats<<<(n_nodes + 255) / 256, 256>>>(atom, n_nodes);
    k_bn<<<1, 64>>>(bnws, bnbs, bnwv, n_nodes);
    k_out<<<(n_nodes * DD + 255) / 256, 256>>>(out, n_nodes);

    int n4 = (n_edges * HED) / 4;
    k_copy<<<(n4 + 255) / 256, 256>>>(ef, out + n_nodes * DD, n4);
}

// round 8
// speedup vs baseline: 1.3674x; 1.3674x over previous
#include <cuda_runtime.h>

#define NSD 16
#define NVD 8
#define HED 32
#define DD  40
#define WND 640
#define MAXN 10000
#define MAXE 160000
#define EPSV 1e-5f
#define TPB2 256
#define NWARP 8
#define CHUNK 64
#define SM_W2 20480
#define SM_W1 1024
#define SM_FLOATS (SM_W2 + SM_W1 + 32 + WND + NWARP * CHUNK * 41)

typedef unsigned long long u64t;

__device__ __constant__ float kC110 = 0.57735026918962576f;
__device__ __constant__ float kC111 = 0.70710678118654752f;

__device__ float    d_qnode[MAXN * DD];
__device__ float    d_attn [MAXE];
__device__ float    d_vedge[MAXE * DD];
__device__ unsigned d_nmax [MAXN];
__device__ float    d_denom[MAXN];
__device__ float    d_upd  [MAXN * DD];
__device__ float    d_ybuf [MAXN * DD];
__device__ float    d_gstats[48];
__device__ float    d_bnp  [48];

__device__ __forceinline__ unsigned encf(float f) {
    unsigned u = __float_as_uint(f);
    return (u & 0x80000000u) ? ~u : (u | 0x80000000u);
}
__device__ __forceinline__ float decf(unsigned u) {
    return (u & 0x80000000u) ? __uint_as_float(u ^ 0x80000000u) : __uint_as_float(~u);
}
__device__ __forceinline__ u64t pk(float lo, float hi) {
    u64t r;
    asm("mov.b64 %0, {%1, %2};" : "=l"(r) : "f"(lo), "f"(hi));
    return r;
}
__device__ __forceinline__ void upk(u64t v, float& lo, float& hi) {
    asm("mov.b64 {%0, %1}, %2;" : "=f"(lo), "=f"(hi) : "l"(v));
}
__device__ __forceinline__ u64t ffma2(u64t a, u64t b, u64t c) {
    u64t d;
    asm("fma.rn.f32x2 %0, %1, %2, %3;" : "=l"(d) : "l"(a), "l"(b), "l"(c));
    return d;
}

__global__ void k_init(int n_nodes) {
    int i = blockIdx.x * blockDim.x + threadIdx.x;
    if (i < n_nodes * DD) d_upd[i] = 0.f;
    if (i < n_nodes) { d_denom[i] = 0.f; d_nmax[i] = 0u; }
    if (i < 48) d_gstats[i] = 0.f;
}

__global__ void k_qnode(const float* __restrict__ atom, const float* __restrict__ Wqs,
                        const float* __restrict__ Wqv, int n_nodes) {
    int n = blockIdx.x * blockDim.x + threadIdx.x;
    if (n >= n_nodes) return;
    const float* a = atom + n * DD;
    float qs[16], qv[24];
#pragma unroll
    for (int o = 0; o < 16; o++) qs[o] = 0.f;
#pragma unroll
    for (int c = 0; c < 24; c++) qv[c] = 0.f;
    for (int i = 0; i < 16; i++) {
        float x = __ldg(a + i);
#pragma unroll
        for (int o = 0; o < 16; o++) qs[o] = fmaf(x, __ldg(Wqs + i * 16 + o), qs[o]);
    }
    for (int i = 0; i < 8; i++) {
        float x0 = __ldg(a + 16 + 3 * i), x1 = __ldg(a + 17 + 3 * i), x2 = __ldg(a + 18 + 3 * i);
#pragma unroll
        for (int o = 0; o < 8; o++) {
            float w = __ldg(Wqv + i * 8 + o);
            qv[3 * o + 0] = fmaf(w, x0, qv[3 * o + 0]);
            qv[3 * o + 1] = fmaf(w, x1, qv[3 * o + 1]);
            qv[3 * o + 2] = fmaf(w, x2, qv[3 * o + 2]);
        }
    }
    float* q = d_qnode + n * DD;
#pragma unroll
    for (int o = 0; o < 16; o++) q[o] = qs[o];
#pragma unroll
    for (int c = 0; c < 24; c++) q[16 + c] = qv[c];
}

// packed GEMV, 2 edges: per j = 1 LDS.128 + 4 FFMA2 (8 MACs)
__device__ __forceinline__ void gemv4_2p(const float* __restrict__ sW2,
                                         const float* __restrict__ sB2,
                                         const u64t* hA2, const u64t* hB2, int n,
                                         u64t& a01, u64t& a23, u64t& b01, u64t& b23) {
    ulonglong2 bb = *reinterpret_cast<const ulonglong2*>(sB2 + n);
    a01 = bb.x; a23 = bb.y; b01 = bb.x; b23 = bb.y;
#pragma unroll
    for (int j = 0; j < HED; j++) {
        ulonglong2 r = *reinterpret_cast<const ulonglong2*>(sW2 + j * WND + n);
        a01 = ffma2(r.x, hA2[j], a01);
        a23 = ffma2(r.y, hA2[j], a23);
        b01 = ffma2(r.x, hB2[j], b01);
        b23 = ffma2(r.y, hB2[j], b23);
    }
}

template <bool IS_K>
__global__ void __launch_bounds__(TPB2, 1) k_edge(
    const float* __restrict__ atom, const float* __restrict__ ef,
    const float* __restrict__ sh, const int* __restrict__ ei,
    const float* __restrict__ W1, const float* __restrict__ B1,
    const float* __restrict__ W2, const float* __restrict__ B2,
    int n_edges)
{
    extern __shared__ float sm[];
    float* sW2 = sm;
    float* sW1 = sm + SM_W2;
    float* sB1 = sW1 + SM_W1;
    float* sB2 = sB1 + 32;
    float* stage = sB2 + WND;
    const int t = threadIdx.x;
    const int wid = t >> 5, lane = t & 31;

    for (int i = t; i < SM_W2 / 4; i += TPB2)
        reinterpret_cast<float4*>(sW2)[i] = __ldg(reinterpret_cast<const float4*>(W2) + i);
    for (int i = t; i < SM_W1 / 4; i += TPB2)
        reinterpret_cast<float4*>(sW1)[i] = __ldg(reinterpret_cast<const float4*>(W1) + i);
    if (t < 32) sB1[t] = __ldg(B1 + t);
    for (int i = t; i < WND; i += TPB2) sB2[i] = __ldg(B2 + i);
    __syncthreads();

    float* wst = stage + wid * (CHUNK * 41);   // this warp's 64-row stage
    const int n_chunks = (n_edges + CHUNK - 1) / CHUNK;

    for (int c = blockIdx.x * NWARP + wid; c < n_chunks; c += gridDim.x * NWARP) {
        const int c0 = c * CHUNK;
        __syncwarp();
        // stage ef: 64 rows x 32 floats, warp-coalesced
        {
            const int lim = n_edges * HED;
            const int gbase = c0 * HED;
#pragma unroll
            for (int l = 0; l < CHUNK * HED; l += 32) {
                int li = l + lane;
                int g = gbase + li;
                wst[(li >> 5) * 41 + lane] = (g < lim) ? __ldg(ef + g) : 0.f;
            }
        }
        __syncwarp();

        // MLP layer 1 for both edges, packed h
        u64t hA2[32], hB2[32];
        {
            float hA[32], hB[32];
            const float* efA = wst + lane * 41;
            const float* efB = wst + (lane + 32) * 41;
#pragma unroll
            for (int j = 0; j < 32; j++) { hA[j] = sB1[j]; hB[j] = sB1[j]; }
#pragma unroll 4
            for (int i = 0; i < 32; i++) {
                float xA = efA[i], xB = efB[i];
#pragma unroll
                for (int j4 = 0; j4 < 8; j4++) {
                    float4 r = *reinterpret_cast<const float4*>(sW1 + i * 32 + 4 * j4);
                    hA[4 * j4 + 0] = fmaf(xA, r.x, hA[4 * j4 + 0]);
                    hA[4 * j4 + 1] = fmaf(xA, r.y, hA[4 * j4 + 1]);
                    hA[4 * j4 + 2] = fmaf(xA, r.z, hA[4 * j4 + 2]);
                    hA[4 * j4 + 3] = fmaf(xA, r.w, hA[4 * j4 + 3]);
                    hB[4 * j4 + 0] = fmaf(xB, r.x, hB[4 * j4 + 0]);
                    hB[4 * j4 + 1] = fmaf(xB, r.y, hB[4 * j4 + 1]);
                    hB[4 * j4 + 2] = fmaf(xB, r.z, hB[4 * j4 + 2]);
                    hB[4 * j4 + 3] = fmaf(xB, r.w, hB[4 * j4 + 3]);
                }
            }
#pragma unroll
            for (int j = 0; j < 32; j++) {
                float a = fmaxf(hA[j], 0.f), b = fmaxf(hB[j], 0.f);
                hA2[j] = pk(a, a);
                hB2[j] = pk(b, b);
            }
        }
        __syncwarp();

        const int eA = c0 + lane, eB = c0 + 32 + lane;
        const bool vA = eA < n_edges, vB = eB < n_edges;
        int srcA = 0, srcB = 0;
        float shsA = 0.f, sA0 = 0.f, sA1 = 0.f, sA2 = 0.f;
        float shsB = 0.f, sB0 = 0.f, sB1f = 0.f, sB2f = 0.f;
        if (vA) {
            int dst = __ldg(ei + eA);
            srcA = __ldg(ei + n_edges + eA);
            float4 s4 = __ldg(reinterpret_cast<const float4*>(sh) + eA);
            shsA = s4.x; sA0 = s4.y; sA1 = s4.z; sA2 = s4.w;
            const float4* ar = reinterpret_cast<const float4*>(atom + dst * DD);
            float* stw = wst + lane * 41;
#pragma unroll
            for (int i = 0; i < 10; i++) {
                float4 v = __ldg(ar + i);
                stw[4 * i] = v.x; stw[4 * i + 1] = v.y; stw[4 * i + 2] = v.z; stw[4 * i + 3] = v.w;
            }
        }
        if (vB) {
            int dst = __ldg(ei + eB);
            srcB = __ldg(ei + n_edges + eB);
            float4 s4 = __ldg(reinterpret_cast<const float4*>(sh) + eB);
            shsB = s4.x; sB0 = s4.y; sB1f = s4.z; sB2f = s4.w;
            const float4* ar = reinterpret_cast<const float4*>(atom + dst * DD);
            float* stw = wst + (lane + 32) * 41;
#pragma unroll
            for (int i = 0; i < 10; i++) {
                float4 v = __ldg(ar + i);
                stw[4 * i] = v.x; stw[4 * i + 1] = v.y; stw[4 * i + 2] = v.z; stw[4 * i + 3] = v.w;
            }
        }
        __syncwarp();

        const float* stA = wst + lane * 41;
        const float* stB = wst + (lane + 32) * 41;

        u64t ospA[8], ospB[8], ovpA[12], ovpB[12];
#pragma unroll
        for (int i = 0; i < 8; i++) { ospA[i] = 0ull; ospB[i] = 0ull; }
#pragma unroll
        for (int i = 0; i < 12; i++) { ovpA[i] = 0ull; ovpB[i] = 0ull; }

#pragma unroll 1
        for (int i2 = 0; i2 < 24; i2++) {
            float aA, aB;
            if (i2 < 16) {
                aA = stA[i2] * shsA;
                aB = stB[i2] * shsB;
            } else {
                const float* xa = stA + 16 + 3 * (i2 - 16);
                const float* xb = stB + 16 + 3 * (i2 - 16);
                aA = kC110 * (xa[0] * sA0 + xa[1] * sA1 + xa[2] * sA2);
                aB = kC110 * (xb[0] * sB0 + xb[1] * sB1f + xb[2] * sB2f);
            }
            u64t aA2 = pk(aA, aA), aB2 = pk(aB, aB);
            const int nb = i2 * 16;
#pragma unroll
            for (int o4 = 0; o4 < 4; o4++) {
                u64t a01, a23, b01, b23;
                gemv4_2p(sW2, sB2, hA2, hB2, nb + 4 * o4, a01, a23, b01, b23);
                ospA[2 * o4 + 0] = ffma2(a01, aA2, ospA[2 * o4 + 0]);
                ospA[2 * o4 + 1] = ffma2(a23, aA2, ospA[2 * o4 + 1]);
                ospB[2 * o4 + 0] = ffma2(b01, aB2, ospB[2 * o4 + 0]);
                ospB[2 * o4 + 1] = ffma2(b23, aB2, ospB[2 * o4 + 1]);
            }
        }
#pragma unroll 1
        for (int i3 = 0; i3 < 32; i3++) {
            float mA0, mA1, mA2, mB0, mB1, mB2;
            if (i3 < 16) {
                float xA = stA[i3], xB = stB[i3];
                mA0 = xA * sA0; mA1 = xA * sA1; mA2 = xA * sA2;
                mB0 = xB * sB0; mB1 = xB * sB1f; mB2 = xB * sB2f;
            } else if (i3 < 24) {
                const float* xa = stA + 16 + 3 * (i3 - 16);
                const float* xb = stB + 16 + 3 * (i3 - 16);
                mA0 = xa[0] * shsA; mA1 = xa[1] * shsA; mA2 = xa[2] * shsA;
                mB0 = xb[0] * shsB; mB1 = xb[1] * shsB; mB2 = xb[2] * shsB;
            } else {
                const float* xa = stA + 16 + 3 * (i3 - 24);
                const float* xb = stB + 16 + 3 * (i3 - 24);
                mA0 = kC111 * (xa[1] * sA2 - xa[2] * sA1);
                mA1 = kC111 * (xa[2] * sA0 - xa[0] * sA2);
                mA2 = kC111 * (xa[0] * sA1 - xa[1] * sA0);
                mB0 = kC111 * (xb[1] * sB2f - xb[2] * sB1f);
                mB1 = kC111 * (xb[2] * sB0 - xb[0] * sB2f);
                mB2 = kC111 * (xb[0] * sB1f - xb[1] * sB0);
            }
            u64t mA0d = pk(mA0, mA0), mA1d = pk(mA1, mA1), mA2d = pk(mA2, mA2);
            u64t mB0d = pk(mB0, mB0), mB1d = pk(mB1, mB1), mB2d = pk(mB2, mB2);
            const int nb = 384 + i3 * 8;
#pragma unroll
            for (int o4 = 0; o4 < 2; o4++) {
                u64t a01, a23, b01, b23;
                gemv4_2p(sW2, sB2, hA2, hB2, nb + 4 * o4, a01, a23, b01, b23);
                const int base = o4 * 6;
                ovpA[base + 0] = ffma2(a01, mA0d, ovpA[base + 0]);
                ovpA[base + 1] = ffma2(a01, mA1d, ovpA[base + 1]);
                ovpA[base + 2] = ffma2(a01, mA2d, ovpA[base + 2]);
                ovpA[base + 3] = ffma2(a23, mA0d, ovpA[base + 3]);
                ovpA[base + 4] = ffma2(a23, mA1d, ovpA[base + 4]);
                ovpA[base + 5] = ffma2(a23, mA2d, ovpA[base + 5]);
                ovpB[base + 0] = ffma2(b01, mB0d, ovpB[base + 0]);
                ovpB[base + 1] = ffma2(b01, mB1d, ovpB[base + 1]);
                ovpB[base + 2] = ffma2(b01, mB2d, ovpB[base + 2]);
                ovpB[base + 3] = ffma2(b23, mB0d, ovpB[base + 3]);
                ovpB[base + 4] = ffma2(b23, mB1d, ovpB[base + 4]);
                ovpB[base + 5] = ffma2(b23, mB2d, ovpB[base + 5]);
            }
        }

        if (IS_K) {
            if (vA) {
                const float* q = d_qnode + srcA * DD;
                float attn = 0.f;
#pragma unroll
                for (int o4 = 0; o4 < 4; o4++)
#pragma unroll
                    for (int hh = 0; hh < 2; hh++) {
                        float lo, hi; upk(ospA[2 * o4 + hh], lo, hi);
                        int o = 4 * o4 + 2 * hh;
                        attn = fmaf(lo, __ldg(q + o), attn);
                        attn = fmaf(hi, __ldg(q + o + 1), attn);
                    }
#pragma unroll
                for (int o4 = 0; o4 < 2; o4++)
#pragma unroll
                    for (int hh = 0; hh < 2; hh++)
#pragma unroll
                        for (int d = 0; d < 3; d++) {
                            float lo, hi; upk(ovpA[o4 * 6 + hh * 3 + d], lo, hi);
                            int o = 4 * o4 + 2 * hh;
                            attn = fmaf(lo, __ldg(q + 16 + 3 * o + d), attn);
                            attn = fmaf(hi, __ldg(q + 16 + 3 * (o + 1) + d), attn);
                        }
                d_attn[eA] = attn;
                atomicMax(&d_nmax[srcA], encf(attn));
            }
            if (vB) {
                const float* q = d_qnode + srcB * DD;
                float attn = 0.f;
#pragma unroll
                for (int o4 = 0; o4 < 4; o4++)
#pragma unroll
                    for (int hh = 0; hh < 2; hh++) {
                        float lo, hi; upk(ospB[2 * o4 + hh], lo, hi);
                        int o = 4 * o4 + 2 * hh;
                        attn = fmaf(lo, __ldg(q + o), attn);
                        attn = fmaf(hi, __ldg(q + o + 1), attn);
                    }
#pragma unroll
                for (int o4 = 0; o4 < 2; o4++)
#pragma unroll
                    for (int hh = 0; hh < 2; hh++)
#pragma unroll
                        for (int d = 0; d < 3; d++) {
                            float lo, hi; upk(ovpB[o4 * 6 + hh * 3 + d], lo, hi);
                            int o = 4 * o4 + 2 * hh;
                            attn = fmaf(lo, __ldg(q + 16 + 3 * o + d), attn);
                            attn = fmaf(hi, __ldg(q + 16 + 3 * (o + 1) + d), attn);
                        }
                d_attn[eB] = attn;
                atomicMax(&d_nmax[srcB], encf(attn));
            }
        } else {
            if (vA) {
#pragma unroll
                for (int o4 = 0; o4 < 4; o4++)
#pragma unroll
                    for (int hh = 0; hh < 2; hh++) {
                        float lo, hi; upk(ospA[2 * o4 + hh], lo, hi);
                        int o = 4 * o4 + 2 * hh;
                        d_vedge[o * n_edges + eA] = lo;
                        d_vedge[(o + 1) * n_edges + eA] = hi;
                    }
#pragma unroll
                for (int o4 = 0; o4 < 2; o4++)
#pragma unroll
                    for (int hh = 0; hh < 2; hh++)
#pragma unroll
                        for (int d = 0; d < 3; d++) {
                            float lo, hi; upk(ovpA[o4 * 6 + hh * 3 + d], lo, hi);
                            int o = 4 * o4 + 2 * hh;
                            d_vedge[(16 + 3 * o + d) * n_edges + eA] = lo;
                            d_vedge[(16 + 3 * (o + 1) + d) * n_edges + eA] = hi;
                        }
            }
            if (vB) {
#pragma unroll
                for (int o4 = 0; o4 < 4; o4++)
#pragma unroll
                    for (int hh = 0; hh < 2; hh++) {
                        float lo, hi; upk(ospB[2 * o4 + hh], lo, hi);
                        int o = 4 * o4 + 2 * hh;
                        d_vedge[o * n_edges + eB] = lo;
                        d_vedge[(o + 1) * n_edges + eB] = hi;
                    }
#pragma unroll
                for (int o4 = 0; o4 < 2; o4++)
#pragma unroll
                    for (int hh = 0; hh < 2; hh++)
#pragma unroll
                        for (int d = 0; d < 3; d++) {
                            float lo, hi; upk(ovpB[o4 * 6 + hh * 3 + d], lo, hi);
                            int o = 4 * o4 + 2 * hh;
                            d_vedge[(16 + 3 * o + d) * n_edges + eB] = lo;
                            d_vedge[(16 + 3 * (o + 1) + d) * n_edges + eB] = hi;
                        }
            }
        }
    }
}

__global__ void k_soft(const int* __restrict__ ei, int n_edges) {
    int e = blockIdx.x * blockDim.x + threadIdx.x;
    if (e >= n_edges) return;
    int src = __ldg(ei + n_edges + e);
    float m = decf(d_nmax[src]);
    float a = expf(d_attn[e] - m);
    atomicAdd(&d_denom[src], a);
    float* u = d_upd + src * DD;
#pragma unroll
    for (int c = 0; c < DD; c++)
        atomicAdd(u + c, a * d_vedge[c * n_edges + e]);
}

__global__ void k_stats(const float* __restrict__ atom, int n_nodes) {
    __shared__ float red[40];
    int t = threadIdx.x;
    if (t < 40) red[t] = 0.f;
    __syncthreads();
    int n = blockIdx.x * blockDim.x + t;
    float y[40];
    if (n < n_nodes) {
        float den = d_denom[n];
        float inv = den > 0.f ? 1.f / den : 0.f;
#pragma unroll
        for (int c = 0; c < 40; c++) {
            y[c] = atom[n * DD + c] + d_upd[n * DD + c] * inv;
            d_ybuf[n * DD + c] = y[c];
        }
    } else {
#pragma unroll
        for (int c = 0; c < 40; c++) y[c] = 0.f;
    }
    const unsigned full = 0xffffffffu;
#pragma unroll
    for (int c = 0; c < 16; c++) {
        float v = y[c], v2 = v * v;
#pragma unroll
        for (int o = 16; o > 0; o >>= 1) {
            v  += __shfl_down_sync(full, v, o);
            v2 += __shfl_down_sync(full, v2, o);
        }
        if ((t & 31) == 0) { atomicAdd(&red[c], v); atomicAdd(&red[16 + c], v2); }
    }
#pragma unroll
    for (int i = 0; i < 8; i++) {
        float v = y[16 + 3 * i] * y[16 + 3 * i] + y[17 + 3 * i] * y[17 + 3 * i]
                + y[18 + 3 * i] * y[18 + 3 * i];
#pragma unroll
        for (int o = 16; o > 0; o >>= 1) v += __shfl_down_sync(full, v, o);
        if ((t & 31) == 0) atomicAdd(&red[32 + i], v);
    }
    __syncthreads();
    if (t < 40) atomicAdd(&d_gstats[t], red[t]);
}

__global__ void k_bn(const float* __restrict__ ws, const float* __restrict__ bs,
                     const float* __restrict__ wv, int n_nodes) {
    int t = threadIdx.x;
    float N = (float)n_nodes;
    if (t < 16) {
        float mu  = d_gstats[t] / N;
        float var = d_gstats[16 + t] / N - mu * mu;
        float A = __ldg(ws + t) / sqrtf(var + EPSV);
        d_bnp[t] = A;
        d_bnp[16 + t] = __ldg(bs + t) - mu * A;
    } else if (t < 24) {
        int i = t - 16;
        float norm = d_gstats[32 + i] / (3.f * N);
        d_bnp[32 + i] = __ldg(wv + i) / sqrtf(norm + EPSV);
    }
}

__global__ void k_out(float* __restrict__ out, int n_nodes) {
    int idx = blockIdx.x * blockDim.x + threadIdx.x;
    if (idx >= n_nodes * DD) return;
    int c = idx % DD;
    float y = d_ybuf[idx];
    out[idx] = (c < 16) ? (y * d_bnp[c] + d_bnp[16 + c])
                        : (y * d_bnp[32 + (c - 16) / 3]);
}

__global__ void k_copy(const float* __restrict__ src, float* __restrict__ dst, int n4) {
    int i = blockIdx.x * blockDim.x + threadIdx.x;
    if (i < n4)
        reinterpret_cast<float4*>(dst)[i] = __ldg(reinterpret_cast<const float4*>(src) + i);
}

extern "C" void kernel_launch(void* const* d_in, const int* in_sizes, int n_in,
                              void* d_out, int out_size) {
    const float* atom = (const float*)d_in[0];
    const float* ef   = (const float*)d_in[1];
    const float* sh   = (const float*)d_in[2];
    const float* Wqs  = (const float*)d_in[3];
    const float* Wqv  = (const float*)d_in[4];
    const float* kw1  = (const float*)d_in[5];
    const float* kb1  = (const float*)d_in[6];
    const float* kw2  = (const float*)d_in[7];
    const float* kb2  = (const float*)d_in[8];
    const float* vw1  = (const float*)d_in[9];
    const float* vb1  = (const float*)d_in[10];
    const float* vw2  = (const float*)d_in[11];
    const float* vb2  = (const float*)d_in[12];
    const float* bnws = (const float*)d_in[13];
    const float* bnbs = (const float*)d_in[14];
    const float* bnwv = (const float*)d_in[15];
    const int*   ei   = (const int*)d_in[16];

    int n_nodes = in_sizes[0] / DD;
    int n_edges = in_sizes[1] / HED;
    float* out = (float*)d_out;

    size_t smem = SM_FLOATS * sizeof(float);
    cudaFuncSetAttribute(k_edge<true>,  cudaFuncAttributeMaxDynamicSharedMemorySize, (int)smem);
    cudaFuncSetAttribute(k_edge<false>, cudaFuncAttributeMaxDynamicSharedMemorySize, (int)smem);

    k_init<<<(n_nodes * DD + 255) / 256, 256>>>(n_nodes);
    k_qnode<<<(n_nodes + 255) / 256, 256>>>(atom, Wqs, Wqv, n_nodes);

    k_edge<true><<<148, TPB2, smem>>>(atom, ef, sh, ei, kw1, kb1, kw2, kb2, n_edges);
    k_edge<false><<<148, TPB2, smem>>>(atom, ef, sh, ei, vw1, vb1, vw2, vb2, n_edges);

    k_soft<<<(n_edges + 255) / 256, 256>>>(ei, n_edges);
    k_stats<<<(n_nodes + 255) / 256, 256>>>(atom, n_nodes);
    k_bn<<<1, 64>>>(bnws, bnbs, bnwv, n_nodes);
    k_out<<<(n_nodes * DD + 255) / 256, 256>>>(out, n_nodes);

    int n4 = (n_edges * HED) / 4;
    k_copy<<<(n4 + 255) / 256, 256>>>(ef, out + n_nodes * DD, n4);
}